// round 1
// baseline (speedup 1.0000x reference)
#include <cuda_runtime.h>
#include <cub/cub.cuh>
#include <cstdint>

// Problem constants (B=8, L=1e6, C=4  ->  size=1349)
#define SPIRAL_SIZE 1349
#define HALF        674            // SPIRAL_SIZE/2
#define NCELL       (SPIRAL_SIZE * SPIRAL_SIZE)   // 1,819,801
#define SIGLEN      1000000
#define NBATCH      8

// libdevice atan2 — the exact function XLA:GPU emits for jnp atan2 on f32.
extern "C" __device__ float __nv_atan2f(float, float);

// Scratch (no allocations allowed => __device__ globals)
__device__ uint32_t g_keys_in[NCELL];
__device__ uint32_t g_vals_in[NCELL];
__device__ uint32_t g_keys_out[NCELL];
__device__ uint32_t g_vals_out[NCELL];
__device__ uint32_t g_rank[NCELL];
__device__ __align__(256) unsigned char g_cub_temp[64u * 1024u * 1024u];

// fl(pi) in float32 = 0x40490FDB
#define PI_F 3.14159274101257324f

// ---------------------------------------------------------------------------
// K1: compute the float32 spiral key bit-exactly as the JAX reference:
//   r    = sqrt(x1*x1 + x2*x2)
//   phi  = acos(x1/r)           (JAX: 2*atan2(sqrt(1-x^2), 1+x); pi at x==-1)
//   phi  = isnan ? 0 : phi
//   phi *= sign(x2)
//   phi += (x2==0 && x1<0) ? pi : 0
//   phi2 = round(r)*2*pi + phi            (round = half-to-even)
// Every op uses explicit round-to-nearest intrinsics so neither fast-math nor
// FMA contraction can perturb the bits.
// ---------------------------------------------------------------------------
__global__ void spiral_keys_kernel(uint32_t* __restrict__ keys,
                                   uint32_t* __restrict__ vals) {
    int s = blockIdx.x * blockDim.x + threadIdx.x;
    if (s >= NCELL) return;

    int j = s % SPIRAL_SIZE;        // x1 index (fast dim, 'xy' meshgrid)
    int i = s / SPIRAL_SIZE;        // x2 index
    float x1 = (float)(j - HALF);
    float x2 = (float)(i - HALF);

    float rr = __fadd_rn(__fmul_rn(x1, x1), __fmul_rn(x2, x2));
    float r  = __fsqrt_rn(rr);
    float xq = __fdiv_rn(x1, r);    // NaN at the center cell (0/0)

    float phi;
    if (xq == -1.0f) {
        phi = PI_F;
    } else {
        // acos(x) = 2 * atan2(sqrt(1 - x*x), 1 + x)   (JAX lax.acos decomposition)
        float t  = __fsub_rn(1.0f, __fmul_rn(xq, xq));
        float sq = __fsqrt_rn(t);
        phi = __fmul_rn(2.0f, __nv_atan2f(sq, __fadd_rn(1.0f, xq)));
    }
    if (isnan(phi)) phi = 0.0f;

    float sgn = (x2 > 0.0f) ? 1.0f : ((x2 < 0.0f) ? -1.0f : 0.0f);
    phi = __fmul_rn(phi, sgn);
    if (x2 == 0.0f && x1 < 0.0f) phi = __fadd_rn(phi, PI_F);

    // phi2 = (round(r) * 2.0) * PI + phi, left-assoc like the Python expr
    float phi2 = __fadd_rn(__fmul_rn(__fmul_rn(rintf(r), 2.0f), PI_F), phi);

    // Monotone float -> uint transform (keys are all >= 0 here, but be safe)
    uint32_t bits = __float_as_uint(phi2);
    bits = (bits & 0x80000000u) ? ~bits : (bits | 0x80000000u);

    keys[s] = bits;
    vals[s] = (uint32_t)s;
}

// K2: invert the sorted permutation. vals_out is a full permutation of
// [0, NCELL), so every rank slot gets written — no init required.
__global__ void spiral_rank_kernel(const uint32_t* __restrict__ vals_out,
                                   uint32_t* __restrict__ rank) {
    int p = blockIdx.x * blockDim.x + threadIdx.x;
    if (p >= NCELL) return;
    rank[vals_out[p]] = (uint32_t)p;
}

// K3: gather. out[b, s, :] = rank[s] < L ? in[b, rank[s], :] : 0
// float4 per (b, cell): writes fully coalesced, reads gathered 16B.
__global__ void spiral_gather_kernel(const float4* __restrict__ in,
                                     float4* __restrict__ out,
                                     const uint32_t* __restrict__ rank) {
    int s = blockIdx.x * blockDim.x + threadIdx.x;
    if (s >= NCELL) return;
    uint32_t r = rank[s];
    bool valid = (r < (uint32_t)SIGLEN);
    float4 z = make_float4(0.0f, 0.0f, 0.0f, 0.0f);
#pragma unroll
    for (int b = 0; b < NBATCH; b++) {
        float4 v = z;
        if (valid) v = __ldg(&in[(size_t)b * SIGLEN + r]);
        out[(size_t)b * NCELL + s] = v;
    }
}

extern "C" void kernel_launch(void* const* d_in, const int* in_sizes, int n_in,
                              void* d_out, int out_size) {
    (void)in_sizes; (void)n_in; (void)out_size;

    void *keys_in, *vals_in, *keys_out, *vals_out, *rankp, *temp;
    cudaGetSymbolAddress(&keys_in,  g_keys_in);
    cudaGetSymbolAddress(&vals_in,  g_vals_in);
    cudaGetSymbolAddress(&keys_out, g_keys_out);
    cudaGetSymbolAddress(&vals_out, g_vals_out);
    cudaGetSymbolAddress(&rankp,    g_rank);
    cudaGetSymbolAddress(&temp,     g_cub_temp);

    const int T = 256;
    const int G = (NCELL + T - 1) / T;

    spiral_keys_kernel<<<G, T>>>((uint32_t*)keys_in, (uint32_t*)vals_in);

    size_t temp_bytes = sizeof(g_cub_temp);
    cub::DeviceRadixSort::SortPairs(temp, temp_bytes,
                                    (const uint32_t*)keys_in,  (uint32_t*)keys_out,
                                    (const uint32_t*)vals_in,  (uint32_t*)vals_out,
                                    NCELL, 0, 32, (cudaStream_t)0);

    spiral_rank_kernel<<<G, T>>>((const uint32_t*)vals_out, (uint32_t*)rankp);

    spiral_gather_kernel<<<G, T>>>((const float4*)d_in[0], (float4*)d_out,
                                   (const uint32_t*)rankp);
}